// round 1
// baseline (speedup 1.0000x reference)
#include <cuda_runtime.h>
#include <cuda_bf16.h>
#include <float.h>

// Problem constants
#define R_ROIS 1000
#define N_CLASS 81
#define N_FG 80
#define IMG_H 600.0f
#define IMG_W 800.0f
#define SCORE_THRESH 0.05f
#define NMS_THRESH 0.5f
#define SORT_N 1024  // padded pow2 for bitonic

// Scratch (no cudaMalloc allowed)
__device__ float g_prob[R_ROIS * N_CLASS];            // softmax probs [R, C]
__device__ float g_bbox[R_ROIS * N_CLASS * 4];        // decoded+clamped boxes [R, C, 4]

// ---------------------------------------------------------------------------
// Kernel A: softmax over classes + box decode + clamp. One thread per RoI.
// ---------------------------------------------------------------------------
__global__ void decode_kernel(const float* __restrict__ roi,
                              const float* __restrict__ roi_loc,
                              const float* __restrict__ roi_score) {
    int r = blockIdx.x * blockDim.x + threadIdx.x;
    if (r >= R_ROIS) return;

    float y0 = roi[r * 4 + 0];
    float x0 = roi[r * 4 + 1];
    float y1 = roi[r * 4 + 2];
    float x1 = roi[r * 4 + 3];
    float h = y1 - y0, w = x1 - x0;
    float cy = y0 + 0.5f * h, cx = x0 + 0.5f * w;

    // softmax(roi_score[r, :])
    const float* sc = roi_score + r * N_CLASS;
    float m = -FLT_MAX;
#pragma unroll 1
    for (int c = 0; c < N_CLASS; c++) m = fmaxf(m, sc[c]);
    float sum = 0.0f;
#pragma unroll 1
    for (int c = 0; c < N_CLASS; c++) sum += expf(sc[c] - m);
    float inv = 1.0f / sum;
#pragma unroll 1
    for (int c = 0; c < N_CLASS; c++) g_prob[r * N_CLASS + c] = expf(sc[c] - m) * inv;

    // decode all classes
    const float* lc = roi_loc + r * N_CLASS * 4;
#pragma unroll 1
    for (int c = 0; c < N_CLASS; c++) {
        float dy = lc[c * 4 + 0] * 0.1f;
        float dx = lc[c * 4 + 1] * 0.1f;
        float dh = lc[c * 4 + 2] * 0.2f;
        float dw = lc[c * 4 + 3] * 0.2f;
        float ny = dy * h + cy;
        float nx = dx * w + cx;
        float nh = expf(dh) * h;
        float nw = expf(dw) * w;
        float by0 = fminf(fmaxf(ny - 0.5f * nh, 0.0f), IMG_H);
        float bx0 = fminf(fmaxf(nx - 0.5f * nw, 0.0f), IMG_W);
        float by1 = fminf(fmaxf(ny + 0.5f * nh, 0.0f), IMG_H);
        float bx1 = fminf(fmaxf(nx + 0.5f * nw, 0.0f), IMG_W);
        float* o = g_bbox + (r * N_CLASS + c) * 4;
        o[0] = by0; o[1] = bx0; o[2] = by1; o[3] = bx1;
    }
}

// ---------------------------------------------------------------------------
// Kernel B: per-class sort + greedy NMS + output. One CTA per foreground class.
// ---------------------------------------------------------------------------
__global__ __launch_bounds__(256) void nms_kernel(float* __restrict__ out,
                                                  float* __restrict__ labels) {
    const int c = blockIdx.x + 1;   // foreground class 1..80
    const int tid = threadIdx.x;
    const int NT = blockDim.x;      // 256

    __shared__ float skey[SORT_N];
    __shared__ int   sidx[SORT_N];
    __shared__ float sb[R_ROIS * 4];
    __shared__ float sarea[R_ROIS];
    __shared__ unsigned char skeep[R_ROIS];
    __shared__ int s_nv;

    // load scores for this class; pad with -inf
    for (int r = tid; r < SORT_N; r += NT) {
        if (r < R_ROIS) { skey[r] = g_prob[r * N_CLASS + c]; }
        else            { skey[r] = -FLT_MAX; }
        sidx[r] = r;
    }
    __syncthreads();

    // bitonic sort, descending by score, ties broken by ascending original idx
    // (matches stable jnp.argsort(-scores); ties are measure-zero anyway)
    for (int k = 2; k <= SORT_N; k <<= 1) {
        for (int j = k >> 1; j > 0; j >>= 1) {
            for (int i = tid; i < SORT_N; i += NT) {
                int ixj = i ^ j;
                if (ixj > i) {
                    float a = skey[i],  b = skey[ixj];
                    int   ia = sidx[i], ib = sidx[ixj];
                    bool desc = ((i & k) == 0);
                    // before(x,y): x precedes y in the final (descending) order
                    bool before_ba = (b > a) || (b == a && ib < ia);
                    bool before_ab = (a > b) || (a == b && ia < ib);
                    bool swp = desc ? before_ba : before_ab;
                    if (swp) {
                        skey[i] = b;  skey[ixj] = a;
                        sidx[i] = ib; sidx[ixj] = ia;
                    }
                }
            }
            __syncthreads();
        }
    }

    // gather boxes in sorted order, compute area / keep init
    for (int r = tid; r < R_ROIS; r += NT) {
        int o = sidx[r];
        const float* bb = g_bbox + (o * N_CLASS + c) * 4;
        float by0 = bb[0], bx0 = bb[1], by1 = bb[2], bx1 = bb[3];
        sb[r * 4 + 0] = by0;
        sb[r * 4 + 1] = bx0;
        sb[r * 4 + 2] = by1;
        sb[r * 4 + 3] = bx1;
        sarea[r] = (by1 - by0) * (bx1 - bx0);
        skeep[r] = (skey[r] > SCORE_THRESH) ? 1 : 0;
    }
    if (tid == 0) s_nv = 0;
    __syncthreads();
    // valid entries form a prefix (sorted descending): count them
    for (int r = tid; r < R_ROIS; r += NT)
        if (skey[r] > SCORE_THRESH) atomicMax(&s_nv, r + 1);
    __syncthreads();
    const int nv = s_nv;

    // greedy NMS over valid prefix only — exactly equivalent to the
    // reference fori_loop over all R (invalid rows suppress nothing,
    // invalid cols are already dead).
    for (int i = 0; i < nv; i++) {
        __syncthreads();
        if (!skeep[i]) continue;   // uniform (shared read after barrier)
        float iy0 = sb[i * 4 + 0], ix0 = sb[i * 4 + 1];
        float iy1 = sb[i * 4 + 2], ix1 = sb[i * 4 + 3];
        float iar = sarea[i];
        for (int jj = i + 1 + tid; jj < nv; jj += NT) {
            if (!skeep[jj]) continue;
            float ty = fmaxf(iy0, sb[jj * 4 + 0]);
            float tx = fmaxf(ix0, sb[jj * 4 + 1]);
            float by = fminf(iy1, sb[jj * 4 + 2]);
            float bx = fminf(ix1, sb[jj * 4 + 3]);
            float wh0 = fmaxf(by - ty, 0.0f);
            float wh1 = fmaxf(bx - tx, 0.0f);
            float inter = wh0 * wh1;
            float iou = inter / (iar + sarea[jj] - inter + 1e-9f);
            if (iou > NMS_THRESH) skeep[jj] = 0;
        }
    }
    __syncthreads();

    // output: out[(c-1), r, 0:5] and labels[(c-1), r]
    float* oc = out + (size_t)(c - 1) * R_ROIS * 5;
    for (int r = tid; r < R_ROIS; r += NT) {
        bool kp = skeep[r] != 0;
        oc[r * 5 + 0] = kp ? sb[r * 4 + 0] : 0.0f;
        oc[r * 5 + 1] = kp ? sb[r * 4 + 1] : 0.0f;
        oc[r * 5 + 2] = kp ? sb[r * 4 + 2] : 0.0f;
        oc[r * 5 + 3] = kp ? sb[r * 4 + 3] : 0.0f;
        oc[r * 5 + 4] = kp ? skey[r]       : 0.0f;
        if (labels)
            labels[(size_t)(c - 1) * R_ROIS + r] = kp ? (float)(c - 1) : -1.0f;
    }
}

extern "C" void kernel_launch(void* const* d_in, const int* in_sizes, int n_in,
                              void* d_out, int out_size) {
    const float* roi       = (const float*)d_in[0];  // [1000,4]
    const float* roi_loc   = (const float*)d_in[1];  // [1000,324]
    const float* roi_score = (const float*)d_in[2];  // [1000,81]

    float* out = (float*)d_out;
    const int out_elems   = N_FG * R_ROIS * 5;  // 400000
    const int label_elems = N_FG * R_ROIS;      // 80000
    float* labels = (out_size >= out_elems + label_elems) ? (out + out_elems)
                                                          : nullptr;

    decode_kernel<<<(R_ROIS + 255) / 256, 256>>>(roi, roi_loc, roi_score);
    nms_kernel<<<N_FG, 256>>>(out, labels);
}

// round 2
// speedup vs baseline: 3.6233x; 3.6233x over previous
#include <cuda_runtime.h>
#include <cuda_bf16.h>
#include <float.h>

#define R_ROIS 1000
#define N_CLASS 81
#define N_FG 80
#define IMG_H 600.0f
#define IMG_W 800.0f
#define SCORE_THRESH 0.05f
#define NMS_THRESH 0.5f
#define CAP 1024   // worst-case valid count per class (<= R_ROIS), pow2 padded

// Scratch (no cudaMalloc allowed): transposed probs [class][roi]
__device__ float g_probT[N_CLASS * R_ROIS];

// ---------------------------------------------------------------------------
// Kernel A: softmax over classes, one WARP per RoI. Coalesced row reads,
// shuffle reductions. Writes transposed so kernel B reads coalesced.
// ---------------------------------------------------------------------------
__global__ __launch_bounds__(256) void softmax_kernel(const float* __restrict__ roi_score) {
    const int warp = (blockIdx.x * blockDim.x + threadIdx.x) >> 5;
    const int lane = threadIdx.x & 31;
    if (warp >= R_ROIS) return;

    const float* sc = roi_score + warp * N_CLASS;
    int c0 = lane, c1 = lane + 32, c2 = lane + 64;
    float s0 = sc[c0];                                   // c0 < 81 always
    float s1 = (c1 < N_CLASS) ? sc[c1] : -FLT_MAX;
    float s2 = (c2 < N_CLASS) ? sc[c2] : -FLT_MAX;

    float m = fmaxf(s0, fmaxf(s1, s2));
#pragma unroll
    for (int o = 16; o > 0; o >>= 1) m = fmaxf(m, __shfl_xor_sync(0xffffffffu, m, o));

    float e0 = expf(s0 - m);
    float e1 = (c1 < N_CLASS) ? expf(s1 - m) : 0.0f;
    float e2 = (c2 < N_CLASS) ? expf(s2 - m) : 0.0f;
    float sum = e0 + e1 + e2;
#pragma unroll
    for (int o = 16; o > 0; o >>= 1) sum += __shfl_xor_sync(0xffffffffu, sum, o);
    float inv = 1.0f / sum;

    g_probT[c0 * R_ROIS + warp] = e0 * inv;
    if (c1 < N_CLASS) g_probT[c1 * R_ROIS + warp] = e1 * inv;
    if (c2 < N_CLASS) g_probT[c2 * R_ROIS + warp] = e2 * inv;
}

// ---------------------------------------------------------------------------
// Kernel B: per-class compaction -> small bitonic sort -> decode survivors ->
// warp-serial NMS -> dense output. One CTA per foreground class.
// ---------------------------------------------------------------------------
__global__ __launch_bounds__(256) void nms_kernel(const float* __restrict__ roi,
                                                  const float* __restrict__ roi_loc,
                                                  float* __restrict__ out,
                                                  float* __restrict__ labels) {
    const int c = blockIdx.x + 1;   // foreground class 1..80
    const int tid = threadIdx.x;
    const int NT = 256;

    __shared__ float skey[CAP];
    __shared__ int   sidx[CAP];
    __shared__ float sb[CAP * 4];
    __shared__ float sarea[CAP];
    __shared__ unsigned char skeep[CAP];
    __shared__ int s_cnt;

    if (tid == 0) s_cnt = 0;
    __syncthreads();

    // 1) compact valid (score, idx); order arbitrary (sort is a total order)
    const float* probc = g_probT + c * R_ROIS;
#pragma unroll 1
    for (int r = tid; r < R_ROIS; r += NT) {
        float p = probc[r];
        if (p > SCORE_THRESH) {
            int pos = atomicAdd(&s_cnt, 1);
            skey[pos] = p;
            sidx[pos] = r;
        }
    }
    __syncthreads();
    const int nv = s_cnt;

    // 2) bitonic sort over next-pow2 >= nv (desc by score, asc idx on ties)
    int P = 1;
    while (P < nv) P <<= 1;
    for (int i = nv + tid; i < P; i += NT) { skey[i] = -FLT_MAX; sidx[i] = 0x7fffffff; }
    __syncthreads();
    for (int k = 2; k <= P; k <<= 1) {
        for (int j = k >> 1; j > 0; j >>= 1) {
            for (int i = tid; i < P; i += NT) {
                int ixj = i ^ j;
                if (ixj > i) {
                    float a = skey[i],  b = skey[ixj];
                    int   ia = sidx[i], ib = sidx[ixj];
                    bool desc = ((i & k) == 0);
                    bool before_ba = (b > a) || (b == a && ib < ia);
                    bool before_ab = (a > b) || (a == b && ia < ib);
                    if (desc ? before_ba : before_ab) {
                        skey[i] = b;  skey[ixj] = a;
                        sidx[i] = ib; sidx[ixj] = ia;
                    }
                }
            }
            __syncthreads();
        }
    }

    // 3) decode boxes ONLY for the nv survivors
#pragma unroll 1
    for (int kk = tid; kk < nv; kk += NT) {
        int r = sidx[kk];
        float y0 = roi[r * 4 + 0];
        float x0 = roi[r * 4 + 1];
        float y1 = roi[r * 4 + 2];
        float x1 = roi[r * 4 + 3];
        float h = y1 - y0, w = x1 - x0;
        float cy = y0 + 0.5f * h, cx = x0 + 0.5f * w;
        const float* lc = roi_loc + r * (N_CLASS * 4) + c * 4;
        float dy = lc[0] * 0.1f;
        float dx = lc[1] * 0.1f;
        float dh = lc[2] * 0.2f;
        float dw = lc[3] * 0.2f;
        float ny = dy * h + cy;
        float nx = dx * w + cx;
        float nh = expf(dh) * h;
        float nw = expf(dw) * w;
        float by0 = fminf(fmaxf(ny - 0.5f * nh, 0.0f), IMG_H);
        float bx0 = fminf(fmaxf(nx - 0.5f * nw, 0.0f), IMG_W);
        float by1 = fminf(fmaxf(ny + 0.5f * nh, 0.0f), IMG_H);
        float bx1 = fminf(fmaxf(nx + 0.5f * nw, 0.0f), IMG_W);
        sb[kk * 4 + 0] = by0;
        sb[kk * 4 + 1] = bx0;
        sb[kk * 4 + 2] = by1;
        sb[kk * 4 + 3] = bx1;
        sarea[kk] = (by1 - by0) * (bx1 - bx0);
        skeep[kk] = 1;
    }
    __syncthreads();

    // 4) greedy NMS, single warp (no block barriers). Exact match to
    //    reference fori_loop restricted to the valid prefix.
    if (tid < 32) {
#pragma unroll 1
        for (int i = 0; i < nv; i++) {
            if (skeep[i]) {
                float iy0 = sb[i * 4 + 0], ix0 = sb[i * 4 + 1];
                float iy1 = sb[i * 4 + 2], ix1 = sb[i * 4 + 3];
                float iar = sarea[i];
#pragma unroll 1
                for (int jj = i + 1 + tid; jj < nv; jj += 32) {
                    if (skeep[jj]) {
                        float ty = fmaxf(iy0, sb[jj * 4 + 0]);
                        float tx = fmaxf(ix0, sb[jj * 4 + 1]);
                        float by = fminf(iy1, sb[jj * 4 + 2]);
                        float bx = fminf(ix1, sb[jj * 4 + 3]);
                        float wh0 = fmaxf(by - ty, 0.0f);
                        float wh1 = fmaxf(bx - tx, 0.0f);
                        float inter = wh0 * wh1;
                        float iou = inter / (iar + sarea[jj] - inter + 1e-9f);
                        if (iou > NMS_THRESH) skeep[jj] = 0;
                    }
                }
            }
            __syncwarp();
        }
    }
    __syncthreads();

    // 5) dense output: rows [0,nv) kept-or-zero, rows [nv,1000) zero / -1
    float* oc = out + (size_t)(c - 1) * R_ROIS * 5;
#pragma unroll 1
    for (int r = tid; r < R_ROIS; r += NT) {
        bool kp = (r < nv) && skeep[r];
        oc[r * 5 + 0] = kp ? sb[r * 4 + 0] : 0.0f;
        oc[r * 5 + 1] = kp ? sb[r * 4 + 1] : 0.0f;
        oc[r * 5 + 2] = kp ? sb[r * 4 + 2] : 0.0f;
        oc[r * 5 + 3] = kp ? sb[r * 4 + 3] : 0.0f;
        oc[r * 5 + 4] = kp ? skey[r]       : 0.0f;
        if (labels)
            labels[(size_t)(c - 1) * R_ROIS + r] = kp ? (float)(c - 1) : -1.0f;
    }
}

extern "C" void kernel_launch(void* const* d_in, const int* in_sizes, int n_in,
                              void* d_out, int out_size) {
    const float* roi       = (const float*)d_in[0];  // [1000,4]
    const float* roi_loc   = (const float*)d_in[1];  // [1000,324]
    const float* roi_score = (const float*)d_in[2];  // [1000,81]

    float* out = (float*)d_out;
    const int out_elems   = N_FG * R_ROIS * 5;  // 400000
    const int label_elems = N_FG * R_ROIS;      // 80000
    float* labels = (out_size >= out_elems + label_elems) ? (out + out_elems)
                                                          : nullptr;

    // 1000 warps for softmax -> 125 CTAs of 256 threads
    softmax_kernel<<<(R_ROIS * 32 + 255) / 256, 256>>>(roi_score);
    nms_kernel<<<N_FG, 256>>>(roi, roi_loc, out, labels);
}